// round 4
// baseline (speedup 1.0000x reference)
#include <cuda_runtime.h>
#include <cuda_bf16.h>
#include <math_constants.h>
#include <cstdint>

#define H 128
#define TILE_M 128
#define GATE_CAP 1100032
#define SEG_CAP  65536

// bf16 tile row stride: 136 elems = 272 B (16B aligned, ldmatrix conflict-free)
#define RSTRIDE 272
#define TILE_BYTES (128 * RSTRIDE)       // 34816

// smem layout (bytes)
#define OFF_B_HI   0
#define OFF_B_LO   34816
#define OFF_A      69632                 // 2 bufs x (hi 34816 + lo 34816)
#define OFF_SGATE  208896                // 4 x 128 floats = 2048
#define OFF_SB1    210944                // 512
#define OFF_SW2    211456                // 512
#define SMEM_TOTAL 211968

__device__ float d_gate[GATE_CAP];
__device__ int   d_seg_start[SEG_CAP];
__device__ int   d_seg_end[SEG_CAP];
__device__ __nv_bfloat16 d_W1hi[H * H];
__device__ __nv_bfloat16 d_W1lo[H * H];

// ---------------------------------------------------------------------------
__device__ __forceinline__ uint32_t smem_u32(const void* p) {
    uint32_t a;
    asm("{ .reg .u64 t; cvta.to.shared.u64 t, %1; cvt.u32.u64 %0, t; }"
        : "=r"(a) : "l"(p));
    return a;
}
__device__ __forceinline__ void ldsm_x4(uint32_t* r, uint32_t addr) {
    asm volatile("ldmatrix.sync.aligned.m8n8.x4.shared.b16 {%0,%1,%2,%3}, [%4];"
                 : "=r"(r[0]), "=r"(r[1]), "=r"(r[2]), "=r"(r[3]) : "r"(addr));
}
__device__ __forceinline__ void ldsm_x4_t(uint32_t* r, uint32_t addr) {
    asm volatile("ldmatrix.sync.aligned.m8n8.x4.trans.shared.b16 {%0,%1,%2,%3}, [%4];"
                 : "=r"(r[0]), "=r"(r[1]), "=r"(r[2]), "=r"(r[3]) : "r"(addr));
}
__device__ __forceinline__ void mma16816(float* d, const uint32_t* a,
                                         const uint32_t* b) {
    asm volatile(
        "mma.sync.aligned.m16n8k16.row.col.f32.bf16.bf16.f32 "
        "{%0,%1,%2,%3}, {%4,%5,%6,%7}, {%8,%9}, {%0,%1,%2,%3};"
        : "+f"(d[0]), "+f"(d[1]), "+f"(d[2]), "+f"(d[3])
        : "r"(a[0]), "r"(a[1]), "r"(a[2]), "r"(a[3]), "r"(b[0]), "r"(b[1]));
}

// ---------------------------------------------------------------------------
// Segment bounds
// ---------------------------------------------------------------------------
__global__ void init_bounds_kernel(int B) {
    int b = blockIdx.x * blockDim.x + threadIdx.x;
    if (b < B) { d_seg_start[b] = -1; d_seg_end[b] = -1; }
}
__global__ void bounds_kernel(const int* __restrict__ bi, int N) {
    int n = blockIdx.x * blockDim.x + threadIdx.x;
    if (n >= N) return;
    int b = bi[n];
    if (n == 0 || bi[n - 1] != b) d_seg_start[b] = n;
    if (n == N - 1 || bi[n + 1] != b) d_seg_end[b] = n + 1;
}

// ---------------------------------------------------------------------------
// W1 -> bf16 hi/lo split (runs once)
// ---------------------------------------------------------------------------
__global__ void prep_w1_kernel(const float* __restrict__ W1) {
    int idx = blockIdx.x * blockDim.x + threadIdx.x;
    if (idx >= H * H) return;
    float v = W1[idx];
    __nv_bfloat16 hi = __float2bfloat16(v);
    __nv_bfloat16 lo = __float2bfloat16(v - __bfloat162float(hi));
    d_W1hi[idx] = hi;
    d_W1lo[idx] = lo;
}

// ---------------------------------------------------------------------------
// Persistent gate kernel: gate[n] = W2 . silu(x[n] @ W1 + b1) + b2
// 512 threads = 16 warps (4M x 4N). Register-staged double buffering:
// prefetch next tile's x into regs while current tile's MMAs run.
// ---------------------------------------------------------------------------
__global__ __launch_bounds__(512, 1) void gate_mma_kernel(
    const float* __restrict__ x, const float* __restrict__ b1,
    const float* __restrict__ W2, const float* __restrict__ b2, int N)
{
    extern __shared__ char smem[];
    const uint32_t sb = smem_u32(smem);
    const int tid = threadIdx.x;
    const int wid = tid >> 5, lane = tid & 31;
    const int warp_m = wid & 3;          // rows warp_m*32
    const int warp_n = wid >> 2;         // cols warp_n*32

    float* sgate = (float*)(smem + OFF_SGATE);
    float* sb1   = (float*)(smem + OFF_SB1);
    float* sw2   = (float*)(smem + OFF_SW2);
    if (tid < H) { sb1[tid] = b1[tid]; sw2[tid] = W2[tid]; }

    // W1 hi/lo -> smem once (padded stride)
#pragma unroll
    for (int it = 0; it < 4; it++) {
        int idx = it * 512 + tid;            // 2048 uint4 per matrix
        int k = idx >> 4;
        int n8 = (idx & 15) << 3;
        uint32_t off = (uint32_t)k * RSTRIDE + (uint32_t)n8 * 2;
        *(uint4*)(smem + OFF_B_HI + off) = *(const uint4*)(d_W1hi + idx * 8);
        *(uint4*)(smem + OFF_B_LO + off) = *(const uint4*)(d_W1lo + idx * 8);
    }

    const float b2v = __ldg(b2);
    const int numTiles = (N + TILE_M - 1) / TILE_M;
    const int grid = gridDim.x;

    // per-thread load mapping: 8 float4 per tile
    const int lr0 = tid >> 5;            // rows lr0 + it*16  (it<8)
    const int lc4 = (tid & 31) << 2;     // col group

    // fragment base offsets
    const uint32_t a_row  = (uint32_t)(warp_m * 32 + (lane & 15));
    const uint32_t a_colb = (uint32_t)((lane >> 4) * 8);
    const uint32_t b_rowk = (uint32_t)(lane & 15);
    const uint32_t b_colb = (uint32_t)(warp_n * 32 + (lane >> 4) * 8);

    // prologue: prefetch first tile into regs
    float4 v[8];
    {
        long base = (long)blockIdx.x * TILE_M;
#pragma unroll
        for (int it = 0; it < 8; it++) {
            long gm = base + lr0 + it * 16;
            v[it] = (gm < N) ? *(const float4*)(x + gm * H + lc4)
                             : make_float4(0.f, 0.f, 0.f, 0.f);
        }
    }

    int i = 0;
    for (int g = blockIdx.x; g < numTiles; g += grid, ++i) {
        const int buf = i & 1;
        char* aHi = smem + OFF_A + buf * (2 * TILE_BYTES);
        char* aLo = aHi + TILE_BYTES;

        // convert + store current regs -> smem buf
#pragma unroll
        for (int it = 0; it < 8; it++) {
            float4 w = v[it];
            __nv_bfloat16 h0 = __float2bfloat16(w.x), h1 = __float2bfloat16(w.y);
            __nv_bfloat16 h2 = __float2bfloat16(w.z), h3 = __float2bfloat16(w.w);
            __nv_bfloat16 l0 = __float2bfloat16(w.x - __bfloat162float(h0));
            __nv_bfloat16 l1 = __float2bfloat16(w.y - __bfloat162float(h1));
            __nv_bfloat16 l2 = __float2bfloat16(w.z - __bfloat162float(h2));
            __nv_bfloat16 l3 = __float2bfloat16(w.w - __bfloat162float(h3));
            uint32_t off = (uint32_t)(lr0 + it * 16) * RSTRIDE + (uint32_t)lc4 * 2;
            uint2 uh, ul;
            uh.x = (uint32_t)__bfloat16_as_ushort(h0) | ((uint32_t)__bfloat16_as_ushort(h1) << 16);
            uh.y = (uint32_t)__bfloat16_as_ushort(h2) | ((uint32_t)__bfloat16_as_ushort(h3) << 16);
            ul.x = (uint32_t)__bfloat16_as_ushort(l0) | ((uint32_t)__bfloat16_as_ushort(l1) << 16);
            ul.y = (uint32_t)__bfloat16_as_ushort(l2) | ((uint32_t)__bfloat16_as_ushort(l3) << 16);
            *(uint2*)(aHi + off) = uh;
            *(uint2*)(aLo + off) = ul;
        }
        __syncthreads();

        // prefetch next tile into regs (LDG in flight during MMA)
        const int gn = g + grid;
        if (gn < numTiles) {
            long base = (long)gn * TILE_M;
#pragma unroll
            for (int it = 0; it < 8; it++) {
                long gm = base + lr0 + it * 16;
                v[it] = (gm < N) ? *(const float4*)(x + gm * H + lc4)
                                 : make_float4(0.f, 0.f, 0.f, 0.f);
            }
        }

        // ---- MMA: 3 products (hi*hi + lo*hi + hi*lo) ----
        float acc[2][4][4];
#pragma unroll
        for (int mi = 0; mi < 2; mi++)
#pragma unroll
            for (int ni = 0; ni < 4; ni++)
#pragma unroll
                for (int r = 0; r < 4; r++) acc[mi][ni][r] = 0.f;

        const uint32_t aHiU = sb + OFF_A + buf * (2 * TILE_BYTES);
        const uint32_t aLoU = aHiU + TILE_BYTES;
        const uint32_t bHiU = sb + OFF_B_HI;
        const uint32_t bLoU = sb + OFF_B_LO;

#pragma unroll
        for (int p = 0; p < 3; p++) {
            const uint32_t aBase = (p == 1) ? aLoU : aHiU;
            const uint32_t bBase = (p == 2) ? bLoU : bHiU;
#pragma unroll
            for (int k = 0; k < 8; k++) {
                uint32_t a[2][4];
#pragma unroll
                for (int mi = 0; mi < 2; mi++)
                    ldsm_x4(a[mi], aBase + (a_row + mi * 16) * RSTRIDE
                                   + (k * 16 + a_colb) * 2);
                uint32_t b[2][4];
#pragma unroll
                for (int nb = 0; nb < 2; nb++)
                    ldsm_x4_t(b[nb], bBase + (k * 16 + b_rowk) * RSTRIDE
                                     + (b_colb + nb * 16) * 2);
#pragma unroll
                for (int mi = 0; mi < 2; mi++)
#pragma unroll
                    for (int nb = 0; nb < 2; nb++) {
                        mma16816(acc[mi][nb * 2],     a[mi], &b[nb][0]);
                        mma16816(acc[mi][nb * 2 + 1], a[mi], &b[nb][2]);
                    }
            }
        }

        // ---- epilogue: silu + dot(W2), reduce ----
        float part[2][2] = {{0.f, 0.f}, {0.f, 0.f}};
#pragma unroll
        for (int mi = 0; mi < 2; mi++)
#pragma unroll
            for (int ni = 0; ni < 4; ni++)
#pragma unroll
                for (int r = 0; r < 4; r++) {
                    int col = warp_n * 32 + ni * 8 + (lane & 3) * 2 + (r & 1);
                    float vv = acc[mi][ni][r] + sb1[col];
                    float sl = vv / (1.f + __expf(-vv));
                    part[mi][r >> 1] = fmaf(sl, sw2[col], part[mi][r >> 1]);
                }
#pragma unroll
        for (int mi = 0; mi < 2; mi++)
#pragma unroll
            for (int hh = 0; hh < 2; hh++) {
                float p = part[mi][hh];
                p += __shfl_xor_sync(0xFFFFFFFF, p, 1);
                p += __shfl_xor_sync(0xFFFFFFFF, p, 2);
                part[mi][hh] = p;
            }
        if ((lane & 3) == 0) {
#pragma unroll
            for (int mi = 0; mi < 2; mi++)
#pragma unroll
                for (int hh = 0; hh < 2; hh++) {
                    int row = warp_m * 32 + mi * 16 + hh * 8 + (lane >> 2);
                    sgate[warp_n * 128 + row] = part[mi][hh];
                }
        }
        __syncthreads();
        if (tid < TILE_M) {
            long gm = (long)g * TILE_M + tid;
            if (gm < N)
                d_gate[gm] = sgate[tid] + sgate[128 + tid]
                           + sgate[256 + tid] + sgate[384 + tid] + b2v;
        }
    }
}

// ---------------------------------------------------------------------------
// Reduce kernel: per-segment mean/max/attention, 2-way unrolled online softmax
// ---------------------------------------------------------------------------
__global__ __launch_bounds__(128) void reduce_kernel(
    const float* __restrict__ x, float* __restrict__ out)
{
    int b = blockIdx.x;
    int j = threadIdx.x;
    int s = d_seg_start[b];
    int e = (s < 0) ? 0 : d_seg_end[b];
    if (s < 0) s = 0;

    float sum = 0.f, mx = -CUDART_INF_F;
    float m0 = -CUDART_INF_F, dn0 = 0.f, ac0 = 0.f;
    float m1 = -CUDART_INF_F, dn1 = 0.f, ac1 = 0.f;

    int n = s;
    for (; n + 2 <= e; n += 2) {
        float xv0 = __ldg(x + (size_t)n * H + j);
        float g0  = d_gate[n];
        float xv1 = __ldg(x + (size_t)(n + 1) * H + j);
        float g1  = d_gate[n + 1];
        sum += xv0 + xv1;
        mx = fmaxf(mx, fmaxf(xv0, xv1));
        if (g0 > m0) { float sc = __expf(m0 - g0); dn0 *= sc; ac0 *= sc; m0 = g0; }
        float e0 = __expf(g0 - m0); dn0 += e0; ac0 = fmaf(e0, xv0, ac0);
        if (g1 > m1) { float sc = __expf(m1 - g1); dn1 *= sc; ac1 *= sc; m1 = g1; }
        float e1 = __expf(g1 - m1); dn1 += e1; ac1 = fmaf(e1, xv1, ac1);
    }
    if (n < e) {
        float xv = __ldg(x + (size_t)n * H + j);
        float g  = d_gate[n];
        sum += xv; mx = fmaxf(mx, xv);
        if (g > m0) { float sc = __expf(m0 - g); dn0 *= sc; ac0 *= sc; m0 = g; }
        float ev = __expf(g - m0); dn0 += ev; ac0 = fmaf(ev, xv, ac0);
    }

    int cnt = e - s;
    float denom = 0.f, acc = 0.f;
    if (cnt > 0) {
        float M  = fmaxf(m0, m1);
        float s0 = (m0 > -CUDART_INF_F) ? __expf(m0 - M) : 0.f;
        float s1 = (m1 > -CUDART_INF_F) ? __expf(m1 - M) : 0.f;
        denom = dn0 * s0 + dn1 * s1;
        acc   = ac0 * s0 + ac1 * s1;
    }
    float* o = out + (size_t)b * (3 * H);
    o[j]         = sum / fmaxf((float)cnt, 1.f);
    o[H + j]     = mx;
    o[2 * H + j] = (cnt > 0) ? (acc / denom) : 0.f;
}

// ---------------------------------------------------------------------------
extern "C" void kernel_launch(void* const* d_in, const int* in_sizes, int n_in,
                              void* d_out, int out_size) {
    const float* x  = (const float*)d_in[0];
    const float* W1 = (const float*)d_in[1];
    const float* b1 = (const float*)d_in[2];
    const float* W2 = (const float*)d_in[3];
    const float* b2 = (const float*)d_in[4];
    const int*   bi = (const int*)d_in[5];

    const int N = in_sizes[5];
    const int B = out_size / (3 * H);
    float* out = (float*)d_out;

    static int inited = 0;
    static int sms = 148;
    if (!inited) {
        cudaFuncSetAttribute(gate_mma_kernel,
                             cudaFuncAttributeMaxDynamicSharedMemorySize, SMEM_TOTAL);
        int dev = 0;
        cudaGetDevice(&dev);
        cudaDeviceGetAttribute(&sms, cudaDevAttrMultiProcessorCount, dev);
        inited = 1;
    }

    const int numTiles = (N + TILE_M - 1) / TILE_M;
    const int gateGrid = sms < numTiles ? sms : numTiles;

    init_bounds_kernel<<<(B + 255) / 256, 256>>>(B);
    bounds_kernel<<<(N + 255) / 256, 256>>>(bi, N);
    prep_w1_kernel<<<(H * H + 255) / 256, 256>>>(W1);
    gate_mma_kernel<<<gateGrid, 512, SMEM_TOTAL>>>(x, b1, W2, b2, N);
    reduce_kernel<<<B, H>>>(x, out);
}

// round 5
// speedup vs baseline: 1.1434x; 1.1434x over previous
#include <cuda_runtime.h>
#include <cuda_bf16.h>
#include <math_constants.h>
#include <cstdint>

#define H 128
#define TILE_M 128
#define NPAD 1048576
#define SEG_CAP 65536

// A tile: 128 rows x 136 bf16 stride (272 B); B half tile: 128 k x 72 bf16 (144 B)
#define RSTRIDE_A 272
#define RSTRIDE_B 144
#define A_BYTES (128 * RSTRIDE_A)        // 34816
#define B_BYTES (128 * RSTRIDE_B)        // 18432

#define OFF_A_HI  0
#define OFF_A_LO  34816
#define OFF_B_HI  69632
#define OFF_B_LO  88064
#define OFF_SGATE 106496                 // 2 x 128 floats = 1024 B
#define OFF_SB1   107520                 // 256 B (64 cols)
#define OFF_SW2   107776                 // 256 B
#define SMEM_TOTAL 108032

__device__ float d_gate2[2 * NPAD];
__device__ int   d_seg_start[SEG_CAP];
__device__ int   d_seg_end[SEG_CAP];
__device__ __nv_bfloat16 d_W1hi[H * H];
__device__ __nv_bfloat16 d_W1lo[H * H];

// ---------------------------------------------------------------------------
__device__ __forceinline__ uint32_t smem_u32(const void* p) {
    uint32_t a;
    asm("{ .reg .u64 t; cvta.to.shared.u64 t, %1; cvt.u32.u64 %0, t; }"
        : "=r"(a) : "l"(p));
    return a;
}
__device__ __forceinline__ void ldsm_x4(uint32_t* r, uint32_t addr) {
    asm volatile("ldmatrix.sync.aligned.m8n8.x4.shared.b16 {%0,%1,%2,%3}, [%4];"
                 : "=r"(r[0]), "=r"(r[1]), "=r"(r[2]), "=r"(r[3]) : "r"(addr));
}
__device__ __forceinline__ void ldsm_x4_t(uint32_t* r, uint32_t addr) {
    asm volatile("ldmatrix.sync.aligned.m8n8.x4.trans.shared.b16 {%0,%1,%2,%3}, [%4];"
                 : "=r"(r[0]), "=r"(r[1]), "=r"(r[2]), "=r"(r[3]) : "r"(addr));
}
__device__ __forceinline__ void mma16816(float* d, const uint32_t* a,
                                         const uint32_t* b) {
    asm volatile(
        "mma.sync.aligned.m16n8k16.row.col.f32.bf16.bf16.f32 "
        "{%0,%1,%2,%3}, {%4,%5,%6,%7}, {%8,%9}, {%0,%1,%2,%3};"
        : "+f"(d[0]), "+f"(d[1]), "+f"(d[2]), "+f"(d[3])
        : "r"(a[0]), "r"(a[1]), "r"(a[2]), "r"(a[3]), "r"(b[0]), "r"(b[1]));
}

// ---------------------------------------------------------------------------
// Segment bounds
// ---------------------------------------------------------------------------
__global__ void init_bounds_kernel(int B) {
    int b = blockIdx.x * blockDim.x + threadIdx.x;
    if (b < B) { d_seg_start[b] = -1; d_seg_end[b] = -1; }
}
__global__ void bounds_kernel(const int* __restrict__ bi, int N) {
    int n = blockIdx.x * blockDim.x + threadIdx.x;
    if (n >= N) return;
    int b = bi[n];
    if (n == 0 || bi[n - 1] != b) d_seg_start[b] = n;
    if (n == N - 1 || bi[n + 1] != b) d_seg_end[b] = n + 1;
}

// ---------------------------------------------------------------------------
// W1 -> bf16 hi/lo split (runs once)
// ---------------------------------------------------------------------------
__global__ void prep_w1_kernel(const float* __restrict__ W1) {
    int idx = blockIdx.x * blockDim.x + threadIdx.x;
    if (idx >= H * H) return;
    float v = W1[idx];
    __nv_bfloat16 hi = __float2bfloat16(v);
    __nv_bfloat16 lo = __float2bfloat16(v - __bfloat162float(hi));
    d_W1hi[idx] = hi;
    d_W1lo[idx] = lo;
}

// ---------------------------------------------------------------------------
// Gate kernel, N-split: CTA (tile, half) computes cols [half*64, half*64+64)
// of h = silu(x@W1+b1) and the partial gate dot with W2. 256 thr, 8 warps
// (4M x 2N), acc 32 regs/thread -> 2 CTAs/SM.
// ---------------------------------------------------------------------------
__global__ __launch_bounds__(256, 2) void gate_mma_kernel(
    const float* __restrict__ x, const float* __restrict__ b1,
    const float* __restrict__ W2, int N)
{
    extern __shared__ char smem[];
    const uint32_t sb = smem_u32(smem);
    const int tid = threadIdx.x;
    const int wid = tid >> 5, lane = tid & 31;
    const int warp_m = wid & 3;          // rows warp_m*32
    const int warp_n = wid >> 2;         // local cols warp_n*32
    const int tile = blockIdx.x >> 1;
    const int half = blockIdx.x & 1;
    const long m0 = (long)tile * TILE_M;

    float* sgate = (float*)(smem + OFF_SGATE);
    float* sb1   = (float*)(smem + OFF_SB1);
    float* sw2   = (float*)(smem + OFF_SW2);
    if (tid < 64) {
        sb1[tid] = b1[half * 64 + tid];
        sw2[tid] = W2[half * 64 + tid];
    }

    // ---- B half (already bf16 hi/lo in gmem, L2-resident) ----
#pragma unroll
    for (int it = 0; it < 4; it++) {
        int idx = it * 256 + tid;        // 1024 uint4 per matrix
        int k = idx >> 3;
        int n8 = (idx & 7) << 3;
        uint32_t off = (uint32_t)k * RSTRIDE_B + (uint32_t)n8 * 2;
        *(uint4*)(smem + OFF_B_HI + off) = *(const uint4*)(d_W1hi + k * H + half * 64 + n8);
        *(uint4*)(smem + OFF_B_LO + off) = *(const uint4*)(d_W1lo + k * H + half * 64 + n8);
    }

    // ---- A tile: x fp32 -> bf16 hi/lo ----
#pragma unroll
    for (int it = 0; it < 16; it++) {
        int idx = it * 256 + tid;
        int r = idx >> 5;
        int c4 = (idx & 31) << 2;
        long gm = m0 + r;
        float4 v = (gm < N) ? *(const float4*)(x + gm * H + c4)
                            : make_float4(0.f, 0.f, 0.f, 0.f);
        __nv_bfloat16 h0 = __float2bfloat16(v.x), h1 = __float2bfloat16(v.y);
        __nv_bfloat16 h2 = __float2bfloat16(v.z), h3 = __float2bfloat16(v.w);
        __nv_bfloat16 l0 = __float2bfloat16(v.x - __bfloat162float(h0));
        __nv_bfloat16 l1 = __float2bfloat16(v.y - __bfloat162float(h1));
        __nv_bfloat16 l2 = __float2bfloat16(v.z - __bfloat162float(h2));
        __nv_bfloat16 l3 = __float2bfloat16(v.w - __bfloat162float(h3));
        uint32_t off = (uint32_t)r * RSTRIDE_A + (uint32_t)c4 * 2;
        uint2 uh, ul;
        uh.x = (uint32_t)__bfloat16_as_ushort(h0) | ((uint32_t)__bfloat16_as_ushort(h1) << 16);
        uh.y = (uint32_t)__bfloat16_as_ushort(h2) | ((uint32_t)__bfloat16_as_ushort(h3) << 16);
        ul.x = (uint32_t)__bfloat16_as_ushort(l0) | ((uint32_t)__bfloat16_as_ushort(l1) << 16);
        ul.y = (uint32_t)__bfloat16_as_ushort(l2) | ((uint32_t)__bfloat16_as_ushort(l3) << 16);
        *(uint2*)(smem + OFF_A_HI + off) = uh;
        *(uint2*)(smem + OFF_A_LO + off) = ul;
    }
    __syncthreads();

    // ---- MMA: 3 products, frags loaded once per k-step ----
    float acc[2][4][4];
#pragma unroll
    for (int mi = 0; mi < 2; mi++)
#pragma unroll
        for (int ni = 0; ni < 4; ni++)
#pragma unroll
            for (int r = 0; r < 4; r++) acc[mi][ni][r] = 0.f;

    const uint32_t a_row  = (uint32_t)(warp_m * 32 + (lane & 15));
    const uint32_t a_colb = (uint32_t)((lane >> 4) * 8);
    const uint32_t b_rowk = (uint32_t)(lane & 15);
    const uint32_t b_colb = (uint32_t)(warp_n * 32 + (lane >> 4) * 8);

#pragma unroll
    for (int k = 0; k < 8; k++) {
        uint32_t ah[2][4], al[2][4];
#pragma unroll
        for (int mi = 0; mi < 2; mi++) {
            uint32_t rowoff = (a_row + mi * 16) * RSTRIDE_A + (k * 16 + a_colb) * 2;
            ldsm_x4(ah[mi], sb + OFF_A_HI + rowoff);
            ldsm_x4(al[mi], sb + OFF_A_LO + rowoff);
        }
        uint32_t bh[2][4], bl[2][4];
#pragma unroll
        for (int nb = 0; nb < 2; nb++) {
            uint32_t rowoff = (k * 16 + b_rowk) * RSTRIDE_B + (b_colb + nb * 16) * 2;
            ldsm_x4_t(bh[nb], sb + OFF_B_HI + rowoff);
            ldsm_x4_t(bl[nb], sb + OFF_B_LO + rowoff);
        }
#pragma unroll
        for (int mi = 0; mi < 2; mi++)
#pragma unroll
            for (int nb = 0; nb < 2; nb++) {
                mma16816(acc[mi][nb * 2],     ah[mi], &bh[nb][0]);   // hi*hi
                mma16816(acc[mi][nb * 2 + 1], ah[mi], &bh[nb][2]);
                mma16816(acc[mi][nb * 2],     al[mi], &bh[nb][0]);   // lo*hi
                mma16816(acc[mi][nb * 2 + 1], al[mi], &bh[nb][2]);
                mma16816(acc[mi][nb * 2],     ah[mi], &bl[nb][0]);   // hi*lo
                mma16816(acc[mi][nb * 2 + 1], ah[mi], &bl[nb][2]);
            }
    }

    // ---- epilogue: silu + dot(W2 slice), warp row-reduce ----
    float part[2][2] = {{0.f, 0.f}, {0.f, 0.f}};
#pragma unroll
    for (int mi = 0; mi < 2; mi++)
#pragma unroll
        for (int ni = 0; ni < 4; ni++)
#pragma unroll
            for (int r = 0; r < 4; r++) {
                int col = warp_n * 32 + ni * 8 + (lane & 3) * 2 + (r & 1);
                float vv = acc[mi][ni][r] + sb1[col];
                float sl = vv / (1.f + __expf(-vv));
                part[mi][r >> 1] = fmaf(sl, sw2[col], part[mi][r >> 1]);
            }
#pragma unroll
    for (int mi = 0; mi < 2; mi++)
#pragma unroll
        for (int hh = 0; hh < 2; hh++) {
            float p = part[mi][hh];
            p += __shfl_xor_sync(0xFFFFFFFF, p, 1);
            p += __shfl_xor_sync(0xFFFFFFFF, p, 2);
            part[mi][hh] = p;
        }
    if ((lane & 3) == 0) {
#pragma unroll
        for (int mi = 0; mi < 2; mi++)
#pragma unroll
            for (int hh = 0; hh < 2; hh++) {
                int row = warp_m * 32 + mi * 16 + hh * 8 + (lane >> 2);
                sgate[warp_n * 128 + row] = part[mi][hh];
            }
    }
    __syncthreads();
    if (tid < TILE_M) {
        long gm = m0 + tid;
        if (gm < N)
            d_gate2[(size_t)half * NPAD + gm] = sgate[tid] + sgate[128 + tid];
    }
}

// ---------------------------------------------------------------------------
// Reduce kernel: per-segment mean/max/attention (b2 cancels in softmax)
// ---------------------------------------------------------------------------
__global__ __launch_bounds__(128) void reduce_kernel(
    const float* __restrict__ x, float* __restrict__ out)
{
    int b = blockIdx.x;
    int j = threadIdx.x;
    int s = d_seg_start[b];
    int e = (s < 0) ? 0 : d_seg_end[b];
    if (s < 0) s = 0;

    float sum = 0.f, mx = -CUDART_INF_F;
    float m0 = -CUDART_INF_F, dn0 = 0.f, ac0 = 0.f;
    float m1 = -CUDART_INF_F, dn1 = 0.f, ac1 = 0.f;

    int n = s;
    for (; n + 2 <= e; n += 2) {
        float xv0 = __ldg(x + (size_t)n * H + j);
        float g0  = d_gate2[n] + d_gate2[NPAD + n];
        float xv1 = __ldg(x + (size_t)(n + 1) * H + j);
        float g1  = d_gate2[n + 1] + d_gate2[NPAD + n + 1];
        sum += xv0 + xv1;
        mx = fmaxf(mx, fmaxf(xv0, xv1));
        if (g0 > m0) { float sc = __expf(m0 - g0); dn0 *= sc; ac0 *= sc; m0 = g0; }
        float e0 = __expf(g0 - m0); dn0 += e0; ac0 = fmaf(e0, xv0, ac0);
        if (g1 > m1) { float sc = __expf(m1 - g1); dn1 *= sc; ac1 *= sc; m1 = g1; }
        float e1 = __expf(g1 - m1); dn1 += e1; ac1 = fmaf(e1, xv1, ac1);
    }
    if (n < e) {
        float xv = __ldg(x + (size_t)n * H + j);
        float g  = d_gate2[n] + d_gate2[NPAD + n];
        sum += xv; mx = fmaxf(mx, xv);
        if (g > m0) { float sc = __expf(m0 - g); dn0 *= sc; ac0 *= sc; m0 = g; }
        float ev = __expf(g - m0); dn0 += ev; ac0 = fmaf(ev, xv, ac0);
    }

    int cnt = e - s;
    float denom = 0.f, acc = 0.f;
    if (cnt > 0) {
        float M  = fmaxf(m0, m1);
        float s0 = (m0 > -CUDART_INF_F) ? __expf(m0 - M) : 0.f;
        float s1 = (m1 > -CUDART_INF_F) ? __expf(m1 - M) : 0.f;
        denom = dn0 * s0 + dn1 * s1;
        acc   = ac0 * s0 + ac1 * s1;
    }
    float* o = out + (size_t)b * (3 * H);
    o[j]         = sum / fmaxf((float)cnt, 1.f);
    o[H + j]     = mx;
    o[2 * H + j] = (cnt > 0) ? (acc / denom) : 0.f;
}

// ---------------------------------------------------------------------------
extern "C" void kernel_launch(void* const* d_in, const int* in_sizes, int n_in,
                              void* d_out, int out_size) {
    const float* x  = (const float*)d_in[0];
    const float* W1 = (const float*)d_in[1];
    const float* b1 = (const float*)d_in[2];
    const float* W2 = (const float*)d_in[3];
    const int*   bi = (const int*)d_in[5];

    const int N = in_sizes[5];
    const int B = out_size / (3 * H);
    float* out = (float*)d_out;

    static int inited = 0;
    if (!inited) {
        cudaFuncSetAttribute(gate_mma_kernel,
                             cudaFuncAttributeMaxDynamicSharedMemorySize, SMEM_TOTAL);
        inited = 1;
    }

    const int numTiles = (N + TILE_M - 1) / TILE_M;

    init_bounds_kernel<<<(B + 255) / 256, 256>>>(B);
    bounds_kernel<<<(N + 255) / 256, 256>>>(bi, N);
    prep_w1_kernel<<<(H * H + 255) / 256, 256>>>(W1);
    gate_mma_kernel<<<numTiles * 2, 256, SMEM_TOTAL>>>(x, b1, W2, N);
    reduce_kernel<<<B, H>>>(x, out);
}